// round 1
// baseline (speedup 1.0000x reference)
#include <cuda_runtime.h>

// norm_conv: out = ((im2col(a) - mean)/std) @ W, fused as
//   conv3x3(a, W) with reflect pad, then (conv - mean*colsum(W)) * rstd
// a: [256, 64, 32, 32] f32, W: [576, 64] f32, out: [256, 64, 32, 32] f32.

#define CCH 32                       // channel chunk
#define SMEM_IN   (CCH * 10 * 34)    // 10880 floats: chunk, 10 padded rows x 34 cols
#define SMEM_W    (CCH * 9 * 64)     // 18432 floats: weight rows for chunk
#define SMEM_FLOATS (SMEM_IN + SMEM_W + 340 + 340 + 256 + 256)
#define SMEM_BYTES  (SMEM_FLOATS * 4)

__device__ float g_wsum[64];

__device__ __forceinline__ int refl(int i) {
    i = (i < 0) ? -i : i;
    return (i >= 32) ? 62 - i : i;
}

__device__ __forceinline__ void fma2(unsigned long long &d,
                                     unsigned long long a,
                                     unsigned long long b) {
    asm("fma.rn.f32x2 %0, %1, %2, %0;" : "+l"(d) : "l"(a), "l"(b));
}

__device__ __forceinline__ unsigned long long pack2(float x) {
    unsigned long long r;
    asm("mov.b64 %0, {%1, %1};" : "=l"(r) : "f"(x));
    return r;
}

__device__ __forceinline__ void unpack2(unsigned long long v, float &lo, float &hi) {
    asm("mov.b64 {%0, %1}, %2;" : "=f"(lo), "=f"(hi) : "l"(v));
}

__global__ void wsum_kernel(const float* __restrict__ w) {
    int o = threadIdx.x;  // 0..63
    float s = 0.f;
    #pragma unroll 8
    for (int p = 0; p < 576; ++p) s += w[p * 64 + o];
    g_wsum[o] = s;
}

__global__ __launch_bounds__(256, 1)
void norm_conv_kernel(const float* __restrict__ a,
                      const float* __restrict__ w,
                      float* __restrict__ out) {
    extern __shared__ float sm[];
    float* in_s   = sm;                  // [CCH][10][34]
    float* w_s    = sm + SMEM_IN;        // [CCH*9][64]
    float* S1     = w_s + SMEM_W;        // [10][34] channel-sum
    float* S2     = S1 + 340;            // [10][34] channel-sumsq
    float* mean_s = S2 + 340;            // [256] per-pixel
    float* rstd_s = mean_s + 256;        // [256]

    const int t    = threadIdx.x;
    const int b    = blockIdx.x >> 2;
    const int row0 = (blockIdx.x & 3) << 3;   // 8-row tile

    const float* A = a + (size_t)b * 64 * 1024;

    // ---- prepass: S1/S2 over padded 10x34 window, all 64 channels ----
    for (int pos = t; pos < 340; pos += 256) {
        int r = pos / 34, col = pos - r * 34;
        int py = refl(row0 - 1 + r), px = refl(col - 1);
        const float* p = A + py * 32 + px;
        float s1 = 0.f, s2 = 0.f;
        #pragma unroll 8
        for (int c = 0; c < 64; ++c) { float v = p[c * 1024]; s1 += v; s2 += v * v; }
        S1[pos] = s1; S2[pos] = s2;
    }
    __syncthreads();
    {   // per-pixel mean / rstd via 3x3 box sums (thread t -> pixel t of tile)
        int tr = t >> 5, col = t & 31;
        float s1 = 0.f, s2 = 0.f;
        #pragma unroll
        for (int dr = 0; dr < 3; ++dr)
            #pragma unroll
            for (int dc = 0; dc < 3; ++dc) {
                int i = (tr + dr) * 34 + col + dc;
                s1 += S1[i]; s2 += S2[i];
            }
        float mean = s1 * (1.f / 576.f);
        float var  = (s2 - s1 * s1 * (1.f / 576.f)) * (1.f / 575.f);
        mean_s[t] = mean;
        rstd_s[t] = rsqrtf(fmaxf(var, 1e-30f));
    }

    // ---- main conv: thread = 4 pixels x 16 out-channels (8 f32x2 pairs) ----
    const int pg = t >> 2;          // pixel group 0..63
    const int ob = (t & 3) << 4;    // out-channel base 0..48
    const int tr = pg >> 3;         // tile row 0..7
    const int c0 = (pg & 7) << 2;   // col base 0..28

    unsigned long long acc[32];     // [pair 0..7][pixel 0..3]
    #pragma unroll
    for (int i = 0; i < 32; ++i) acc[i] = 0ull;

    for (int ch0 = 0; ch0 < 64; ch0 += CCH) {
        __syncthreads();
        // stage input chunk (reflect-padded)
        for (int idx = t; idx < CCH * 340; idx += 256) {
            int c = idx / 340, rem = idx - c * 340;
            int r = rem / 34, col = rem - r * 34;
            int py = refl(row0 - 1 + r), px = refl(col - 1);
            in_s[idx] = A[(ch0 + c) * 1024 + py * 32 + px];
        }
        // stage weight chunk (contiguous rows [ch0*9, ch0*9+288))
        {
            const float4* Wg = (const float4*)(w + (size_t)ch0 * 9 * 64);
            float4* Ws = (float4*)w_s;
            for (int idx = t; idx < CCH * 9 * 16; idx += 256) Ws[idx] = Wg[idx];
        }
        __syncthreads();

        const float* ipb = in_s + tr * 34 + c0;
        const float* wpb = w_s + ob;
        for (int c = 0; c < CCH; ++c) {
            const float* ip = ipb + c * 340;
            const float* wp = wpb + c * 9 * 64;
            #pragma unroll
            for (int tap = 0; tap < 9; ++tap) {
                const int dy = tap / 3, dx = tap - dy * 3;
                const float* ipt = ip + dy * 34 + dx;
                unsigned long long x0 = pack2(ipt[0]);
                unsigned long long x1 = pack2(ipt[1]);
                unsigned long long x2 = pack2(ipt[2]);
                unsigned long long x3 = pack2(ipt[3]);
                const ulonglong2* wv = (const ulonglong2*)(wp + tap * 64);
                ulonglong2 wa = wv[0], wb = wv[1], wc = wv[2], wd = wv[3];
                unsigned long long wr[8] = {wa.x, wa.y, wb.x, wb.y,
                                            wc.x, wc.y, wd.x, wd.y};
                #pragma unroll
                for (int k = 0; k < 8; ++k) {
                    fma2(acc[k * 4 + 0], wr[k], x0);
                    fma2(acc[k * 4 + 1], wr[k], x1);
                    fma2(acc[k * 4 + 2], wr[k], x2);
                    fma2(acc[k * 4 + 3], wr[k], x3);
                }
            }
        }
    }

    // ---- epilogue: (acc - mean*wsum)*rstd, vectorized stores ----
    const int pbase = tr * 32 + c0;
    const float m0 = mean_s[pbase],     m1 = mean_s[pbase + 1],
                m2 = mean_s[pbase + 2], m3 = mean_s[pbase + 3];
    const float r0 = rstd_s[pbase],     r1 = rstd_s[pbase + 1],
                r2 = rstd_s[pbase + 2], r3 = rstd_s[pbase + 3];

    float* obase = out + (size_t)b * 64 * 1024 + (row0 + tr) * 32 + c0;
    #pragma unroll
    for (int k = 0; k < 8; ++k) {
        int o0 = ob + 2 * k;
        float ws0 = g_wsum[o0], ws1 = g_wsum[o0 + 1];
        float4 v0, v1; float lo, hi;
        unpack2(acc[k * 4 + 0], lo, hi);
        v0.x = (lo - m0 * ws0) * r0;  v1.x = (hi - m0 * ws1) * r0;
        unpack2(acc[k * 4 + 1], lo, hi);
        v0.y = (lo - m1 * ws0) * r1;  v1.y = (hi - m1 * ws1) * r1;
        unpack2(acc[k * 4 + 2], lo, hi);
        v0.z = (lo - m2 * ws0) * r2;  v1.z = (hi - m2 * ws1) * r2;
        unpack2(acc[k * 4 + 3], lo, hi);
        v0.w = (lo - m3 * ws0) * r3;  v1.w = (hi - m3 * ws1) * r3;
        *(float4*)(obase + (size_t)o0 * 1024)       = v0;
        *(float4*)(obase + (size_t)(o0 + 1) * 1024) = v1;
    }
}

extern "C" void kernel_launch(void* const* d_in, const int* in_sizes, int n_in,
                              void* d_out, int out_size) {
    const float* a = (const float*)d_in[0];   // [256,64,32,32]
    const float* w = (const float*)d_in[1];   // [576,64]
    float* out = (float*)d_out;

    cudaFuncSetAttribute(norm_conv_kernel,
                         cudaFuncAttributeMaxDynamicSharedMemorySize, SMEM_BYTES);

    wsum_kernel<<<1, 64>>>(w);
    norm_conv_kernel<<<256 * 4, 256, SMEM_BYTES>>>(a, w, out);
}

// round 3
// speedup vs baseline: 2.7417x; 2.7417x over previous
#include <cuda_runtime.h>
#include <cuda_bf16.h>
#include <cstdint>

// norm_conv via mma.sync bf16-split implicit GEMM (base PTX, no tcgen05).
// out = ((im2col(a)-mean)/std) @ W == (conv3x3(a,W) - mean*colsum(W)) * rstd
// Per CTA: 128-pixel tile (4 rows) of one batch. 8 warps, each 16 pixels x 64 out.
// 9 taps; per tap K=64 channels; 3 bf16-split products per mma position.

#define SM_WSUM 0                    // 64 f
#define SM_MEAN 256                  // 128 f
#define SM_RSTD 768                  // 128 f
#define SM_S1   1280                 // 204 f
#define SM_S2   2096                 // 204 f
#define SM_B0   3072                 // 2 x B_BYTES (double buffer)
#define B_BYTES 18432                // per tap: hi[64][72] + lo[64][72] bf16
#define SM_IN   (SM_B0 + 2 * B_BYTES)          // 39936
#define IN_CS   210                  // floats per channel row (6*34=204, padded)
#define SMEM_TOTAL (SM_IN + 64 * IN_CS * 4)    // 93696 bytes

__device__ float g_wsum[64];
__device__ __align__(16) __nv_bfloat16 g_wtp[9 * 2 * 64 * 72]; // [tap][hl][o][k]

__device__ __forceinline__ int refl(int i) {
    i = (i < 0) ? -i : i;
    return (i >= 32) ? 62 - i : i;
}

#define CVT_BF16X2(res, f0, f1) \
    asm("cvt.rn.satfinite.bf16x2.f32 %0, %1, %2;" : "=r"(res) : "f"(f1), "f"(f0))

#define CP_ASYNC16(dst, src) \
    asm volatile("cp.async.cg.shared.global [%0], [%1], 16;" \
                 :: "r"(dst), "l"(src) : "memory")
#define CP_COMMIT() asm volatile("cp.async.commit_group;" ::: "memory")
#define CP_WAIT(n)  asm volatile("cp.async.wait_group %0;" :: "n"(n) : "memory")

#define MMA16816(c, a0, a1, a2, a3, b0, b1) \
    asm volatile("mma.sync.aligned.m16n8k16.row.col.f32.bf16.bf16.f32 " \
        "{%0,%1,%2,%3}, {%4,%5,%6,%7}, {%8,%9}, {%0,%1,%2,%3};" \
        : "+f"((c)[0]), "+f"((c)[1]), "+f"((c)[2]), "+f"((c)[3]) \
        : "r"(a0), "r"(a1), "r"(a2), "r"(a3), "r"(b0), "r"(b1))

__global__ void wsum_kernel(const float* __restrict__ w) {
    int o = threadIdx.x;
    float s = 0.f;
    #pragma unroll 8
    for (int p = 0; p < 576; ++p) s += w[p * 64 + o];
    g_wsum[o] = s;
}

// g_wtp[tap][hl][o][k]: hi/lo bf16 split of W[(k*9+tap)*64 + o], k padded to 72.
__global__ void wt_prep_kernel(const float* __restrict__ w) {
    int idx = blockIdx.x * 256 + threadIdx.x;
    if (idx >= 9 * 2 * 64 * 72) return;
    int k = idx % 72;
    int rest = idx / 72;
    int o = rest & 63;
    rest >>= 6;
    int hl = rest & 1, tap = rest >> 1;
    __nv_bfloat16 v = __float2bfloat16(0.f);
    if (k < 64) {
        float f = w[(k * 9 + tap) * 64 + o];
        __nv_bfloat16 hi = __float2bfloat16(f);
        v = (hl == 0) ? hi : __float2bfloat16(f - __bfloat162float(hi));
    }
    g_wtp[idx] = v;
}

__global__ __launch_bounds__(256, 2)
void conv_mma_kernel(const float* __restrict__ a, float* __restrict__ out) {
    extern __shared__ char smem[];
    float* smf = (float*)smem;
    uint32_t sb;
    asm("{ .reg .u64 t; cvta.to.shared.u64 t, %1; cvt.u32.u64 %0, t; }"
        : "=r"(sb) : "l"(smem));

    const int t = threadIdx.x;
    const int wrp = t >> 5, l = t & 31;
    const int b = blockIdx.x >> 3;
    const int row0 = (blockIdx.x & 7) << 2;
    const float* A = a + (size_t)b * 65536;
    float* in_s = smf + SM_IN / 4;

    // prefetch B tap0 (group 0)
    {
        const char* src = (const char*)g_wtp;
        for (int i = t; i < B_BYTES / 16; i += 256)
            CP_ASYNC16(sb + SM_B0 + i * 16, __cvta_generic_to_global(src + i * 16));
        CP_COMMIT();
    }
    if (t < 64) smf[SM_WSUM / 4 + t] = g_wsum[t];

    // stage input tile [64 ch][6 rows x 34 cols], reflect padded
    for (int idx = t; idx < 64 * 204; idx += 256) {
        int c = idx / 204, rem = idx - c * 204;
        int ry = rem / 34, cx = rem - ry * 34;
        int py = refl(row0 - 1 + ry), px = refl(cx - 1);
        in_s[c * IN_CS + rem] = A[c * 1024 + py * 32 + px];
    }
    __syncthreads();

    // stats: channel reduce then 3x3 box sums
    if (t < 204) {
        float s1 = 0.f, s2 = 0.f;
        #pragma unroll 8
        for (int c = 0; c < 64; ++c) {
            float v = in_s[c * IN_CS + t];
            s1 += v; s2 += v * v;
        }
        smf[SM_S1 / 4 + t] = s1;
        smf[SM_S2 / 4 + t] = s2;
    }
    __syncthreads();
    if (t < 128) {
        int r = t >> 5, x = t & 31;
        float s1 = 0.f, s2 = 0.f;
        #pragma unroll
        for (int dr = 0; dr < 3; ++dr)
            #pragma unroll
            for (int dc = 0; dc < 3; ++dc) {
                int i = (r + dr) * 34 + x + dc;
                s1 += smf[SM_S1 / 4 + i];
                s2 += smf[SM_S2 / 4 + i];
            }
        float mean = s1 * (1.f / 576.f);
        float var  = (s2 - s1 * s1 * (1.f / 576.f)) * (1.f / 575.f);
        smf[SM_MEAN / 4 + t] = mean;
        smf[SM_RSTD / 4 + t] = rsqrtf(fmaxf(var, 1e-30f));
    }

    // warp tile: pixels [wrp*16, wrp*16+16), all 64 out channels
    const int g = l >> 2, tg = l & 3;
    const int p0 = wrp * 16 + g, p1 = p0 + 8;
    const int r0g = p0 >> 5, x0g = p0 & 31;
    const int r1g = p1 >> 5, x1g = p1 & 31;

    float acc[8][4];
    #pragma unroll
    for (int i = 0; i < 8; ++i)
        #pragma unroll
        for (int j = 0; j < 4; ++j) acc[i][j] = 0.f;

    int buf = 0;
    for (int tap = 0; tap < 9; ++tap) {
        if (tap < 8) {   // prefetch next tap into other buffer
            const char* src = (const char*)g_wtp + (size_t)(tap + 1) * B_BYTES;
            uint32_t dst = sb + SM_B0 + (buf ^ 1) * B_BYTES;
            for (int i = t; i < B_BYTES / 16; i += 256)
                CP_ASYNC16(dst + i * 16, __cvta_generic_to_global(src + i * 16));
            CP_COMMIT();
            CP_WAIT(1);
        } else {
            CP_WAIT(0);
        }
        __syncthreads();

        const int dy = tap / 3, dx = tap - dy * 3;
        const int base0 = (r0g + dy) * 34 + x0g + dx;
        const int base1 = (r1g + dy) * 34 + x1g + dx;
        const char* Bh = smem + SM_B0 + buf * B_BYTES;  // [64][72] bf16 hi
        const char* Bl = Bh + 9216;                     // lo

        #pragma unroll
        for (int kc = 0; kc < 4; ++kc) {
            const int c0 = kc * 16 + tg * 2;
            const float* pc = in_s + c0 * IN_CS;
            float f00 = pc[base0],              f10 = pc[base1];
            float f01 = pc[IN_CS + base0],      f11 = pc[IN_CS + base1];
            float f02 = pc[8 * IN_CS + base0],  f12 = pc[8 * IN_CS + base1];
            float f03 = pc[9 * IN_CS + base0],  f13 = pc[9 * IN_CS + base1];

            uint32_t ah0, ah1, ah2, ah3, al0, al1, al2, al3;
            CVT_BF16X2(ah0, f00, f01);
            CVT_BF16X2(ah1, f10, f11);
            CVT_BF16X2(ah2, f02, f03);
            CVT_BF16X2(ah3, f12, f13);
            {
                float h0 = __uint_as_float(ah0 << 16);
                float h1 = __uint_as_float(ah0 & 0xffff0000u);
                CVT_BF16X2(al0, f00 - h0, f01 - h1);
                h0 = __uint_as_float(ah1 << 16);
                h1 = __uint_as_float(ah1 & 0xffff0000u);
                CVT_BF16X2(al1, f10 - h0, f11 - h1);
                h0 = __uint_as_float(ah2 << 16);
                h1 = __uint_as_float(ah2 & 0xffff0000u);
                CVT_BF16X2(al2, f02 - h0, f03 - h1);
                h0 = __uint_as_float(ah3 << 16);
                h1 = __uint_as_float(ah3 & 0xffff0000u);
                CVT_BF16X2(al3, f12 - h0, f13 - h1);
            }

            #pragma unroll
            for (int nc = 0; nc < 8; ++nc) {
                // B frag: b0 = {B[k][n], B[k+1][n]}, b1 = {B[k+8][n], B[k+9][n]}
                // smem layout [n][k] k-contiguous, row stride 72 elems (144 B)
                const int boff = ((nc * 8 + g) * 72 + kc * 16 + tg * 2) * 2;
                uint32_t b0h = *(const uint32_t*)(Bh + boff);
                uint32_t b1h = *(const uint32_t*)(Bh + boff + 16);
                uint32_t b0l = *(const uint32_t*)(Bl + boff);
                uint32_t b1l = *(const uint32_t*)(Bl + boff + 16);
                MMA16816(acc[nc], ah0, ah1, ah2, ah3, b0h, b1h);
                MMA16816(acc[nc], ah0, ah1, ah2, ah3, b0l, b1l);
                MMA16816(acc[nc], al0, al1, al2, al3, b0h, b1h);
            }
        }
        buf ^= 1;
        __syncthreads();
    }

    // epilogue: (acc - mean*wsum) * rstd
    const int offp0 = row0 * 32 + p0;
    const int offp1 = row0 * 32 + p1;
    const float mean0 = smf[SM_MEAN / 4 + p0], rstd0 = smf[SM_RSTD / 4 + p0];
    const float mean1 = smf[SM_MEAN / 4 + p1], rstd1 = smf[SM_RSTD / 4 + p1];
    float* ob = out + (size_t)b * 65536;
    #pragma unroll
    for (int nc = 0; nc < 8; ++nc) {
        const int o0 = nc * 8 + tg * 2;
        const float ws0 = smf[SM_WSUM / 4 + o0];
        const float ws1 = smf[SM_WSUM / 4 + o0 + 1];
        ob[(size_t)o0 * 1024 + offp0]       = (acc[nc][0] - mean0 * ws0) * rstd0;
        ob[(size_t)(o0 + 1) * 1024 + offp0] = (acc[nc][1] - mean0 * ws1) * rstd0;
        ob[(size_t)o0 * 1024 + offp1]       = (acc[nc][2] - mean1 * ws0) * rstd1;
        ob[(size_t)(o0 + 1) * 1024 + offp1] = (acc[nc][3] - mean1 * ws1) * rstd1;
    }
}

extern "C" void kernel_launch(void* const* d_in, const int* in_sizes, int n_in,
                              void* d_out, int out_size) {
    const float* a = (const float*)d_in[0];   // [256,64,32,32]
    const float* w = (const float*)d_in[1];   // [576,64]
    float* out = (float*)d_out;

    cudaFuncSetAttribute(conv_mma_kernel,
                         cudaFuncAttributeMaxDynamicSharedMemorySize, SMEM_TOTAL);

    wsum_kernel<<<1, 64>>>(w);
    wt_prep_kernel<<<324, 256>>>(w);
    conv_mma_kernel<<<2048, 256, SMEM_TOTAL>>>(a, out);
}

// round 4
// speedup vs baseline: 3.3296x; 1.2144x over previous
#include <cuda_runtime.h>
#include <cuda_bf16.h>
#include <cstdint>

// norm_conv via mma.sync bf16-split implicit GEMM.
// out = ((im2col(a)-mean)/std) @ W == (conv3x3(a,W) - mean*colsum(W)) * rstd
// Per CTA: 128-pixel tile (4 rows) of one batch, 8 warps x (16 pix x 64 out).
// Input pre-split into bf16 hi/lo planes (pixel-major) once; 9 taps of
// K=64 GEMM accumulation, B via ldmatrix, 3-term bf16 split products.

#define SM_WSUM 0                      // 64 f
#define SM_MEAN 256                    // 128 f
#define SM_RSTD 768                    // 128 f
#define SM_S1   1280                   // 204 f
#define SM_S2   2096                   // 204 f
#define SM_B0   3072                   // 2 x B_BYTES double buffer
#define B_BYTES 18432                  // per tap: hi[64][72] + lo[64][72] bf16
#define SM_HI   (SM_B0 + 2 * B_BYTES)  // 39936: [204 pix][36 words] bf16x2
#define SM_LO   (SM_HI + 204 * 36 * 4) // 69312
#define SMEM_TOTAL (SM_LO + 204 * 36 * 4)   // 98688 bytes -> 2 CTAs/SM
#define IN_W    36                     // u32 words per pixel row (64ch + pad)

__device__ float g_wsum[64];
__device__ __align__(16) __nv_bfloat16 g_wtp[9 * 2 * 64 * 72]; // [tap][hl][o][k]

__device__ __forceinline__ int refl(int i) {
    i = (i < 0) ? -i : i;
    return (i >= 32) ? 62 - i : i;
}

#define CVT_BF16X2(res, f0, f1) \
    asm("cvt.rn.satfinite.bf16x2.f32 %0, %1, %2;" : "=r"(res) : "f"(f1), "f"(f0))

#define CP_ASYNC16(dst, src) \
    asm volatile("cp.async.cg.shared.global [%0], [%1], 16;" \
                 :: "r"(dst), "l"(src) : "memory")
#define CP_COMMIT() asm volatile("cp.async.commit_group;" ::: "memory")
#define CP_WAIT(n)  asm volatile("cp.async.wait_group %0;" :: "n"(n) : "memory")

#define MMA16816(c, a0, a1, a2, a3, b0, b1) \
    asm volatile("mma.sync.aligned.m16n8k16.row.col.f32.bf16.bf16.f32 " \
        "{%0,%1,%2,%3}, {%4,%5,%6,%7}, {%8,%9}, {%0,%1,%2,%3};" \
        : "+f"((c)[0]), "+f"((c)[1]), "+f"((c)[2]), "+f"((c)[3]) \
        : "r"(a0), "r"(a1), "r"(a2), "r"(a3), "r"(b0), "r"(b1))

#define LDSM_X4(r0, r1, r2, r3, addr) \
    asm volatile("ldmatrix.sync.aligned.m8n8.x4.shared.b16 {%0,%1,%2,%3}, [%4];" \
        : "=r"(r0), "=r"(r1), "=r"(r2), "=r"(r3) : "r"(addr))

__global__ void wsum_kernel(const float* __restrict__ w) {
    int o = blockIdx.x, l = threadIdx.x;
    float s = 0.f;
    for (int p = l; p < 576; p += 32) s += w[p * 64 + o];
    #pragma unroll
    for (int d = 16; d; d >>= 1) s += __shfl_xor_sync(0xffffffffu, s, d);
    if (l == 0) g_wsum[o] = s;
}

// g_wtp[tap][hl][o][k]: hi/lo bf16 split of W[(k*9+tap)*64 + o], k padded to 72.
__global__ void wt_prep_kernel(const float* __restrict__ w) {
    int idx = blockIdx.x * 256 + threadIdx.x;
    if (idx >= 9 * 2 * 64 * 72) return;
    int k = idx % 72;
    int rest = idx / 72;
    int o = rest & 63;
    rest >>= 6;
    int hl = rest & 1, tap = rest >> 1;
    __nv_bfloat16 v = __float2bfloat16(0.f);
    if (k < 64) {
        float f = w[(k * 9 + tap) * 64 + o];
        __nv_bfloat16 hi = __float2bfloat16(f);
        v = (hl == 0) ? hi : __float2bfloat16(f - __bfloat162float(hi));
    }
    g_wtp[idx] = v;
}

__global__ __launch_bounds__(256, 2)
void conv_mma_kernel(const float* __restrict__ a, float* __restrict__ out) {
    extern __shared__ char smem[];
    float* smf = (float*)smem;
    uint32_t sb;
    asm("{ .reg .u64 t; cvta.to.shared.u64 t, %1; cvt.u32.u64 %0, t; }"
        : "=r"(sb) : "l"(smem));

    const int t = threadIdx.x;
    const int wrp = t >> 5, l = t & 31;
    const int b = blockIdx.x >> 3;
    const int row0 = (blockIdx.x & 7) << 2;
    const float* A = a + (size_t)b * 65536;

    // prefetch B tap0 into buffer 0
    {
        const char* src = (const char*)g_wtp;
        for (int i = t; i < B_BYTES / 16; i += 256)
            CP_ASYNC16(sb + SM_B0 + i * 16, __cvta_generic_to_global(src + i * 16));
        CP_COMMIT();
    }
    if (t < 64) smf[SM_WSUM / 4 + t] = g_wsum[t];

    // stage + bf16-split input tile into pixel-major hi/lo planes.
    // word (pix, cw) holds channels (2cw, 2cw+1) of pixel pix.
    {
        uint32_t* hip = (uint32_t*)(smem + SM_HI);
        uint32_t* lop = (uint32_t*)(smem + SM_LO);
        for (int idx = t; idx < 32 * 204; idx += 256) {
            int cw = idx / 204, pix = idx - cw * 204;
            int ry = pix / 34, cx = pix - ry * 34;
            int py = refl(row0 - 1 + ry), px = refl(cx - 1);
            const float* p = A + (2 * cw) * 1024 + py * 32 + px;
            float f0 = p[0], f1 = p[1024];
            uint32_t hx; CVT_BF16X2(hx, f0, f1);
            float h0 = __uint_as_float(hx << 16);
            float h1 = __uint_as_float(hx & 0xffff0000u);
            uint32_t lx; CVT_BF16X2(lx, f0 - h0, f1 - h1);
            hip[pix * IN_W + cw] = hx;
            lop[pix * IN_W + cw] = lx;
        }
    }
    __syncthreads();

    // stats: channel reduce (reconstruct v = hi + lo), then 3x3 box sums
    if (t < 204) {
        const uint32_t* hip = (const uint32_t*)(smem + SM_HI) + t * IN_W;
        const uint32_t* lop = (const uint32_t*)(smem + SM_LO) + t * IN_W;
        float s1 = 0.f, s2 = 0.f;
        #pragma unroll 8
        for (int w = 0; w < 32; ++w) {
            uint32_t hx = hip[w], lx = lop[w];
            float f0 = __uint_as_float(hx << 16) + __uint_as_float(lx << 16);
            float f1 = __uint_as_float(hx & 0xffff0000u) +
                       __uint_as_float(lx & 0xffff0000u);
            s1 += f0 + f1;
            s2 += f0 * f0 + f1 * f1;
        }
        smf[SM_S1 / 4 + t] = s1;
        smf[SM_S2 / 4 + t] = s2;
    }
    __syncthreads();
    if (t < 128) {
        int r = t >> 5, x = t & 31;
        float s1 = 0.f, s2 = 0.f;
        #pragma unroll
        for (int dr = 0; dr < 3; ++dr)
            #pragma unroll
            for (int dc = 0; dc < 3; ++dc) {
                int i = (r + dr) * 34 + x + dc;
                s1 += smf[SM_S1 / 4 + i];
                s2 += smf[SM_S2 / 4 + i];
            }
        float mean = s1 * (1.f / 576.f);
        float var  = (s2 - s1 * s1 * (1.f / 576.f)) * (1.f / 575.f);
        smf[SM_MEAN / 4 + t] = mean;
        smf[SM_RSTD / 4 + t] = rsqrtf(fmaxf(var, 1e-30f));
    }

    // warp tile: pixels [wrp*16, wrp*16+16), all 64 out channels
    const int g = l >> 2, tg = l & 3;
    const int p0 = wrp * 16 + g, p1 = p0 + 8;
    const int r0g = p0 >> 5, x0g = p0 & 31;
    const int r1g = p1 >> 5, x1g = p1 & 31;

    // ldmatrix lane offset: tile = l>>3 -> (nc-sub = tile>>1, half = tile&1)
    // row bytes: ((tile>>1)*8 + (l&7))*144 + (tile&1)*16, + j*2304 + kc*32
    const uint32_t lds_lane =
        (uint32_t)((((l >> 4) & 1) * 8 + (l & 7)) * 144 + ((l >> 3) & 1) * 16);

    float acc[8][4];
    #pragma unroll
    for (int i = 0; i < 8; ++i)
        #pragma unroll
        for (int j = 0; j < 4; ++j) acc[i][j] = 0.f;

    int buf = 0;
    for (int tap = 0; tap < 9; ++tap) {
        if (tap < 8) {
            const char* src = (const char*)g_wtp + (size_t)(tap + 1) * B_BYTES;
            uint32_t dst = sb + SM_B0 + (buf ^ 1) * B_BYTES;
            for (int i = t; i < B_BYTES / 16; i += 256)
                CP_ASYNC16(dst + i * 16, __cvta_generic_to_global(src + i * 16));
            CP_COMMIT();
            CP_WAIT(1);
        } else {
            CP_WAIT(0);
        }
        __syncthreads();

        const int dy = tap / 3, dx = tap - dy * 3;
        const int base0 = ((r0g + dy) * 34 + x0g + dx) * IN_W;
        const int base1 = ((r1g + dy) * 34 + x1g + dx) * IN_W;
        const uint32_t* hip = (const uint32_t*)(smem + SM_HI);
        const uint32_t* lop = (const uint32_t*)(smem + SM_LO);
        const uint32_t bhb = sb + SM_B0 + buf * B_BYTES + lds_lane;
        const uint32_t blb = bhb + 9216;

        #pragma unroll
        for (int kc = 0; kc < 4; ++kc) {
            const int wo = kc * 8 + tg;
            uint32_t ah0 = hip[base0 + wo],     ah1 = hip[base1 + wo];
            uint32_t ah2 = hip[base0 + wo + 4], ah3 = hip[base1 + wo + 4];
            uint32_t al0 = lop[base0 + wo],     al1 = lop[base1 + wo];
            uint32_t al2 = lop[base0 + wo + 4], al3 = lop[base1 + wo + 4];

            uint32_t bh[16], bl[16];
            #pragma unroll
            for (int j = 0; j < 4; ++j) {
                uint32_t addr = j * 2304u + kc * 32u;
                LDSM_X4(bh[4 * j], bh[4 * j + 1], bh[4 * j + 2], bh[4 * j + 3],
                        bhb + addr);
                LDSM_X4(bl[4 * j], bl[4 * j + 1], bl[4 * j + 2], bl[4 * j + 3],
                        blb + addr);
            }
            #pragma unroll
            for (int nc = 0; nc < 8; ++nc) {
                MMA16816(acc[nc], ah0, ah1, ah2, ah3, bh[nc * 2], bh[nc * 2 + 1]);
                MMA16816(acc[nc], ah0, ah1, ah2, ah3, bl[nc * 2], bl[nc * 2 + 1]);
                MMA16816(acc[nc], al0, al1, al2, al3, bh[nc * 2], bh[nc * 2 + 1]);
            }
        }
        buf ^= 1;
        __syncthreads();
    }

    // epilogue: (acc - mean*wsum) * rstd
    const int offp0 = row0 * 32 + p0;
    const int offp1 = row0 * 32 + p1;
    const float mean0 = smf[SM_MEAN / 4 + p0], rstd0 = smf[SM_RSTD / 4 + p0];
    const float mean1 = smf[SM_MEAN / 4 + p1], rstd1 = smf[SM_RSTD / 4 + p1];
    float* ob = out + (size_t)b * 65536;
    #pragma unroll
    for (int nc = 0; nc < 8; ++nc) {
        const int o0 = nc * 8 + tg * 2;
        const float ws0 = smf[SM_WSUM / 4 + o0];
        const float ws1 = smf[SM_WSUM / 4 + o0 + 1];
        ob[(size_t)o0 * 1024 + offp0]       = (acc[nc][0] - mean0 * ws0) * rstd0;
        ob[(size_t)(o0 + 1) * 1024 + offp0] = (acc[nc][1] - mean0 * ws1) * rstd0;
        ob[(size_t)o0 * 1024 + offp1]       = (acc[nc][2] - mean1 * ws0) * rstd1;
        ob[(size_t)(o0 + 1) * 1024 + offp1] = (acc[nc][3] - mean1 * ws1) * rstd1;
    }
}

extern "C" void kernel_launch(void* const* d_in, const int* in_sizes, int n_in,
                              void* d_out, int out_size) {
    const float* a = (const float*)d_in[0];   // [256,64,32,32]
    const float* w = (const float*)d_in[1];   // [576,64]
    float* out = (float*)d_out;

    cudaFuncSetAttribute(conv_mma_kernel,
                         cudaFuncAttributeMaxDynamicSharedMemorySize, SMEM_TOTAL);

    wsum_kernel<<<64, 32>>>(w);
    wt_prep_kernel<<<324, 256>>>(w);
    conv_mma_kernel<<<2048, 256, SMEM_TOTAL>>>(a, out);
}